// round 9
// baseline (speedup 1.0000x reference)
#include <cuda_runtime.h>
#include <cstdint>

#define TILE_WORDS 8192
#define NTHREADS   512
#define WPT        (TILE_WORDS / NTHREADS)   // 16 words per thread
#define VECS       (WPT / 4)                 // 4 uint4 per thread
#define NWARPS     (NTHREADS / 32)

// constants from the reference (only the h2 stream reaches the output)
#define FMIX_C1 2246822507u
#define FMIX_C2 3266489909u
#define POS_B   374761393u
#define SEED    608135816u

// fmix32 with right-shifts done as IMAD.HI (fma pipe) instead of SHF (alu
// pipe) to balance pipe load. m16 = 2^16, m19 = 2^19 arrive as runtime args
// so ptxas cannot strength-reduce the multiplies back into shifts.
__device__ __forceinline__ uint32_t fmix32_bal(uint32_t x, uint32_t m16, uint32_t m19) {
    x ^= __umulhi(x, m16);    // x >> 16
    x *= FMIX_C1;
    x ^= __umulhi(x, m19);    // x >> 13
    x *= FMIX_C2;
    x ^= __umulhi(x, m16);    // x >> 16
    return x;
}

__device__ __forceinline__ uint32_t fmix32(uint32_t x) {  // scalar epilogue use
    x ^= x >> 16; x *= FMIX_C1;
    x ^= x >> 13; x *= FMIX_C2;
    x ^= x >> 16;
    return x;
}

// One word, h2 stream only (output = int64 hash truncated to int32 = h2_final).
__device__ __forceinline__ void hash_step(uint32_t v, uint32_t i, uint32_t s2,
                                          uint32_t m16, uint32_t m19,
                                          uint32_t& h2) {
    uint32_t a2 = i * POS_B + s2;                 // IMAD  (fma)
    uint32_t r2 = __funnelshift_l(i, i, 13);      // SHF   (alu)
    h2 += fmix32_bal(v ^ a2 ^ r2, m16, m19);      // LOP3 fuses v^a^r (alu)
}

__global__ void __launch_bounds__(NTHREADS, 4)
hash_tiles_kernel(const uint32_t* __restrict__ in,
                  float* __restrict__ out,
                  uint32_t n, uint32_t m16, uint32_t m19) {
    const uint32_t tile = blockIdx.x;
    const uint32_t base = tile * TILE_WORDS;
    const uint32_t tid  = threadIdx.x;

    const uint32_t s2 = (uint32_t)((SEED * 2654435761u) ^ 3735928559u);

    uint32_t h2 = 0u;

    if (base + TILE_WORDS <= n) {
        // fast path: full tile; 4 coalesced uint4 loads per thread, batched up
        // front (evict-first: single-touch streaming data)
        const uint4* inv = reinterpret_cast<const uint4*>(in + base);
        uint4 v[VECS];
        #pragma unroll
        for (int j = 0; j < VECS; ++j) {
            v[j] = __ldcs(&inv[(uint32_t)j * NTHREADS + tid]);
        }
        #pragma unroll
        for (int j = 0; j < VECS; ++j) {
            uint32_t i0 = base + ((uint32_t)j * NTHREADS + tid) * 4u;
            hash_step(v[j].x, i0 + 0u, s2, m16, m19, h2);
            hash_step(v[j].y, i0 + 1u, s2, m16, m19, h2);
            hash_step(v[j].z, i0 + 2u, s2, m16, m19, h2);
            hash_step(v[j].w, i0 + 3u, s2, m16, m19, h2);
        }
    } else {
        // ragged tail tile: scalar guarded (not hit for n % TILE == 0)
        for (uint32_t w = tid; w < TILE_WORDS; w += NTHREADS) {
            uint32_t i = base + w;
            if (i < n) {
                uint32_t a2 = i * POS_B + s2;
                uint32_t r2 = __funnelshift_l(i, i, 13);
                h2 += fmix32(in[i] ^ a2 ^ r2);
            }
        }
    }

    // warp reduction (wrapping uint32 adds)
    #pragma unroll
    for (int o = 16; o > 0; o >>= 1) {
        h2 += __shfl_down_sync(0xffffffffu, h2, o);
    }

    __shared__ uint32_t sh2[NWARPS];
    if ((tid & 31u) == 0u) sh2[tid >> 5] = h2;
    __syncthreads();

    if (tid == 0) {
        uint32_t b = 0u;
        #pragma unroll
        for (int w = 0; w < NWARPS; ++w) b += sh2[w];
        uint32_t nbytes = n * 4u;          // wrapping, matches (n*4) & 0xFFFFFFFF
        b = fmix32(b ^ nbytes);            // h2_final = low word of int64 hash
        // Output = int64 hash truncated to int32, value-cast to float32.
        out[tile] = (float)(int32_t)b;
    }
}

extern "C" void kernel_launch(void* const* d_in, const int* in_sizes, int n_in,
                              void* d_out, int out_size) {
    const uint32_t* in = (const uint32_t*)d_in[0];
    float* out = (float*)d_out;
    uint32_t n = (uint32_t)in_sizes[0];
    uint32_t n_tiles = (n + TILE_WORDS - 1) / TILE_WORDS;
    hash_tiles_kernel<<<n_tiles, NTHREADS>>>(in, out, n, 1u << 16, 1u << 19);
}

// round 10
// speedup vs baseline: 1.1356x; 1.1356x over previous
#include <cuda_runtime.h>
#include <cstdint>

#define TILE_WORDS 8192
#define NTHREADS   512
#define WPT        (TILE_WORDS / NTHREADS)   // 16 words per thread
#define VECS       (WPT / 4)                 // 4 uint4 per thread
#define NWARPS     (NTHREADS / 32)

// constants from the reference (only the h2 stream reaches the output)
#define FMIX_C1 2246822507u
#define FMIX_C2 3266489909u
#define POS_B   374761393u
#define SEED    608135816u

__device__ __forceinline__ uint32_t fmix32(uint32_t x) {
    x ^= x >> 16; x *= FMIX_C1;
    x ^= x >> 13; x *= FMIX_C2;
    x ^= x >> 16;
    return x;
}

// One word, h2 stream only (output = int64 hash truncated to int32 = h2_final).
// fmix chain stays pure alu/fma same-pipe (R9 showed cross-pipe hops lengthen
// the serial chain); only the accumulate is moved to the slack fma pipe via
// IMAD with a runtime-opaque multiplier of 1.
__device__ __forceinline__ void hash_step(uint32_t v, uint32_t i, uint32_t s2,
                                          uint32_t one, uint32_t& h2) {
    uint32_t a2 = i * POS_B + s2;                 // IMAD  (fma)
    uint32_t r2 = __funnelshift_l(i, i, 13);      // SHF   (alu)
    uint32_t x  = fmix32(v ^ a2 ^ r2);            // LOP3 fuses v^a^r
    h2 = x * one + h2;                            // IMAD  (fma) accumulate
}

__global__ void __launch_bounds__(NTHREADS, 3)
hash_tiles_kernel(const uint32_t* __restrict__ in,
                  float* __restrict__ out,
                  uint32_t n, uint32_t one) {
    const uint32_t tile = blockIdx.x;
    const uint32_t base = tile * TILE_WORDS;
    const uint32_t tid  = threadIdx.x;

    const uint32_t s2 = (uint32_t)((SEED * 2654435761u) ^ 3735928559u);

    uint32_t h2 = 0u;

    if (base + TILE_WORDS <= n) {
        // fast path: full tile; 4 coalesced uint4 loads per thread, batched up
        // front (evict-first: single-touch streaming data)
        const uint4* inv = reinterpret_cast<const uint4*>(in + base);
        uint4 v[VECS];
        #pragma unroll
        for (int j = 0; j < VECS; ++j) {
            v[j] = __ldcs(&inv[(uint32_t)j * NTHREADS + tid]);
        }
        #pragma unroll
        for (int j = 0; j < VECS; ++j) {
            uint32_t i0 = base + ((uint32_t)j * NTHREADS + tid) * 4u;
            hash_step(v[j].x, i0 + 0u, s2, one, h2);
            hash_step(v[j].y, i0 + 1u, s2, one, h2);
            hash_step(v[j].z, i0 + 2u, s2, one, h2);
            hash_step(v[j].w, i0 + 3u, s2, one, h2);
        }
    } else {
        // ragged tail tile: scalar guarded (not hit for n % TILE == 0)
        for (uint32_t w = tid; w < TILE_WORDS; w += NTHREADS) {
            uint32_t i = base + w;
            if (i < n) {
                uint32_t a2 = i * POS_B + s2;
                uint32_t r2 = __funnelshift_l(i, i, 13);
                h2 += fmix32(in[i] ^ a2 ^ r2);
            }
        }
    }

    // warp reduction (wrapping uint32 adds)
    #pragma unroll
    for (int o = 16; o > 0; o >>= 1) {
        h2 += __shfl_down_sync(0xffffffffu, h2, o);
    }

    __shared__ uint32_t sh2[NWARPS];
    if ((tid & 31u) == 0u) sh2[tid >> 5] = h2;
    __syncthreads();

    if (tid == 0) {
        uint32_t b = 0u;
        #pragma unroll
        for (int w = 0; w < NWARPS; ++w) b += sh2[w];
        uint32_t nbytes = n * 4u;          // wrapping, matches (n*4) & 0xFFFFFFFF
        b = fmix32(b ^ nbytes);            // h2_final = low word of int64 hash
        // Output = int64 hash truncated to int32, value-cast to float32.
        out[tile] = (float)(int32_t)b;
    }
}

extern "C" void kernel_launch(void* const* d_in, const int* in_sizes, int n_in,
                              void* d_out, int out_size) {
    const uint32_t* in = (const uint32_t*)d_in[0];
    float* out = (float*)d_out;
    uint32_t n = (uint32_t)in_sizes[0];
    uint32_t n_tiles = (n + TILE_WORDS - 1) / TILE_WORDS;
    hash_tiles_kernel<<<n_tiles, NTHREADS>>>(in, out, n, 1u);
}

// round 11
// speedup vs baseline: 1.1420x; 1.0056x over previous
#include <cuda_runtime.h>
#include <cstdint>

#define TILE_WORDS 8192
#define NTHREADS   512
#define WPT        (TILE_WORDS / NTHREADS)   // 16 words per thread
#define VECS       (WPT / 4)                 // 4 uint4 per thread
#define NWARPS     (NTHREADS / 32)

// constants from the reference (only the h2 stream reaches the output)
#define FMIX_C1 2246822507u
#define FMIX_C2 3266489909u
#define POS_B   374761393u
#define SEED    608135816u

__device__ __forceinline__ uint32_t fmix32(uint32_t x) {
    x ^= x >> 16; x *= FMIX_C1;
    x ^= x >> 13; x *= FMIX_C2;
    x ^= x >> 16;
    return x;
}

// One word, h2 stream only (output = int64 hash truncated to int32 = h2_final).
// Accumulate rides the slack fma pipe via IMAD with runtime-opaque one.
__device__ __forceinline__ void hash_step(uint32_t v, uint32_t i, uint32_t s2,
                                          uint32_t one, uint32_t& acc) {
    uint32_t a2 = i * POS_B + s2;                 // IMAD  (fma)
    uint32_t r2 = __funnelshift_l(i, i, 13);      // SHF   (alu)
    uint32_t x  = fmix32(v ^ a2 ^ r2);            // LOP3 fuses v^a^r
    acc = x * one + acc;                          // IMAD  (fma) accumulate
}

__global__ void __launch_bounds__(NTHREADS, 4)
hash_tiles_kernel(const uint32_t* __restrict__ in,
                  float* __restrict__ out,
                  uint32_t n, uint32_t one) {
    const uint32_t tile = blockIdx.x;
    const uint32_t base = tile * TILE_WORDS;
    const uint32_t tid  = threadIdx.x;

    const uint32_t s2 = (uint32_t)((SEED * 2654435761u) ^ 3735928559u);

    uint32_t h2a = 0u, h2b = 0u;   // dual accumulators (wrapping add commutes)

    if (base + TILE_WORDS <= n) {
        // fast path: full tile; 4 coalesced uint4 loads per thread, batched up
        // front (evict-first: single-touch streaming data)
        const uint4* inv = reinterpret_cast<const uint4*>(in + base);
        uint4 v[VECS];
        #pragma unroll
        for (int j = 0; j < VECS; ++j) {
            v[j] = __ldcs(&inv[(uint32_t)j * NTHREADS + tid]);
        }
        #pragma unroll
        for (int j = 0; j < VECS; ++j) {
            uint32_t i0 = base + ((uint32_t)j * NTHREADS + tid) * 4u;
            hash_step(v[j].x, i0 + 0u, s2, one, h2a);
            hash_step(v[j].y, i0 + 1u, s2, one, h2b);
            hash_step(v[j].z, i0 + 2u, s2, one, h2a);
            hash_step(v[j].w, i0 + 3u, s2, one, h2b);
        }
    } else {
        // ragged tail tile: scalar guarded (not hit for n % TILE == 0)
        for (uint32_t w = tid; w < TILE_WORDS; w += NTHREADS) {
            uint32_t i = base + w;
            if (i < n) {
                uint32_t a2 = i * POS_B + s2;
                uint32_t r2 = __funnelshift_l(i, i, 13);
                h2a += fmix32(in[i] ^ a2 ^ r2);
            }
        }
    }

    uint32_t h2 = h2a + h2b;

    // warp reduction (wrapping uint32 adds)
    #pragma unroll
    for (int o = 16; o > 0; o >>= 1) {
        h2 += __shfl_down_sync(0xffffffffu, h2, o);
    }

    __shared__ uint32_t sh2[NWARPS];
    if ((tid & 31u) == 0u) sh2[tid >> 5] = h2;
    __syncthreads();

    if (tid == 0) {
        uint32_t b = 0u;
        #pragma unroll
        for (int w = 0; w < NWARPS; ++w) b += sh2[w];
        uint32_t nbytes = n * 4u;          // wrapping, matches (n*4) & 0xFFFFFFFF
        b = fmix32(b ^ nbytes);            // h2_final = low word of int64 hash
        // Output = int64 hash truncated to int32, value-cast to float32.
        out[tile] = (float)(int32_t)b;
    }
}

extern "C" void kernel_launch(void* const* d_in, const int* in_sizes, int n_in,
                              void* d_out, int out_size) {
    const uint32_t* in = (const uint32_t*)d_in[0];
    float* out = (float*)d_out;
    uint32_t n = (uint32_t)in_sizes[0];
    uint32_t n_tiles = (n + TILE_WORDS - 1) / TILE_WORDS;
    hash_tiles_kernel<<<n_tiles, NTHREADS>>>(in, out, n, 1u);
}